// round 1
// baseline (speedup 1.0000x reference)
#include <cuda_runtime.h>
#include <math.h>

// ---------------- problem constants ----------------
#define BB 4
#define FFR 16          // frames
#define CC 3
#define HH 96
#define WW 128
#define PATP 8
#define HPP 12
#define WPP 16
#define NNS 192         // HPP*WPP tokens per frame
#define TT (BB*FFR*NNS) // 12288 total tokens
#define DIMM 512
#define NHEADS 8
#define DHH 64
#define NDEPTH 4
#define FFHID 2048
#define PATCH_K (PATP*PATP*CC) // 192
#define QSCALE 0.125f          // 64^-0.5

// ---------------- device scratch (no allocation allowed) ----------------
__device__ float g_x[TT*DIMM];
__device__ float g_y[TT*DIMM];
__device__ float g_qkv[(size_t)TT*3*DIMM];
__device__ float g_attn[TT*DIMM];
__device__ float g_h1[(size_t)TT*2*FFHID];
__device__ float g_gate[(size_t)TT*FFHID];
__device__ float g_sim[(size_t)BB*NHEADS*FFR*NNS*NNS]; // 18.9M floats
__device__ float g_patch[(size_t)TT*PATCH_K];
__device__ float g_fsin[FFR*DHH], g_fcos[FFR*DHH];
__device__ float g_isin[NNS*DHH], g_icos[NNS*DHH];

// ---------------- rope tables ----------------
__global__ void rope_frame_kernel() {
    int idx = blockIdx.x*blockDim.x + threadIdx.x;
    if (idx >= FFR*DHH) return;
    int f = idx / DHH, j = idx % DHH;
    int i = j & 31;
    float inv = expf(-((float)(2*i)/64.f) * logf(10000.f));
    float a = (float)f * inv;
    g_fsin[idx] = sinf(a);
    g_fcos[idx] = cosf(a);
}

__global__ void rope_image_kernel() {
    int idx = blockIdx.x*blockDim.x + threadIdx.x;
    if (idx >= NNS*DHH) return;
    int n = idx / DHH, j = idx % DHH;
    int half = j >> 1;
    int hp = n / WPP, wp = n % WPP;
    const float PI = 3.14159265358979323846f;
    const float LOG2_5 = 2.3219280948873623f;
    float ang;
    if (half < 16) {
        float sc = exp2f((float)half * (LOG2_5/15.f));
        float hl = -1.f + 2.f*(float)hp/11.f;
        ang = hl * sc * PI;
    } else {
        float sc = exp2f((float)(half-16) * (LOG2_5/15.f));
        float wl = -1.f + 2.f*(float)wp/15.f;
        ang = wl * sc * PI;
    }
    g_isin[idx] = sinf(ang);
    g_icos[idx] = cosf(ang);
}

// ---------------- patchify rearrange ----------------
__global__ void patchify_kernel(const float* __restrict__ video) {
    int idx = blockIdx.x*blockDim.x + threadIdx.x;
    if (idx >= TT*PATCH_K) return;
    int t = idx / PATCH_K, k = idx % PATCH_K;
    int n = t % NNS;
    int bf = t / NNS;                 // b*F + f
    int hp = n / WPP, wp = n % WPP;
    int p1 = k / (PATP*CC);
    int rem = k % (PATP*CC);
    int p2 = rem / CC;
    int c = rem % CC;
    g_patch[idx] = video[ (((size_t)(bf*CC + c))*HH + hp*PATP + p1)*WW + wp*PATP + p2 ];
}

// ---------------- generic SGEMM: C = A(MxK) @ B(KxN) [+bias][+res] ----------------
__global__ __launch_bounds__(256) void sgemm_kernel(
    const float* __restrict__ A, const float* __restrict__ B,
    const float* __restrict__ bias, const float* __restrict__ res,
    float* __restrict__ C, int M, int N, int K)
{
    __shared__ float As[16][68];   // transposed tile, padded
    __shared__ float Bs[16][64];
    int bx = blockIdx.x, by = blockIdx.y;
    int tid = threadIdx.x;
    int tx = tid & 15, ty = tid >> 4;
    float acc[4][4] = {};
    const float* Ap = A + (size_t)by*64*K;
    const float* Bp = B + bx*64;
    int arow = tid >> 2;
    int acol = (tid & 3) << 2;
    int brow = tid >> 4;
    int bcol = (tid & 15) << 2;
    for (int k0 = 0; k0 < K; k0 += 16) {
        float4 a4 = *reinterpret_cast<const float4*>(Ap + (size_t)arow*K + k0 + acol);
        As[acol+0][arow] = a4.x;
        As[acol+1][arow] = a4.y;
        As[acol+2][arow] = a4.z;
        As[acol+3][arow] = a4.w;
        float4 b4 = *reinterpret_cast<const float4*>(Bp + (size_t)(k0+brow)*N + bcol);
        Bs[brow][bcol+0] = b4.x;
        Bs[brow][bcol+1] = b4.y;
        Bs[brow][bcol+2] = b4.z;
        Bs[brow][bcol+3] = b4.w;
        __syncthreads();
        #pragma unroll
        for (int k = 0; k < 16; k++) {
            float av[4], bv[4];
            #pragma unroll
            for (int i = 0; i < 4; i++) av[i] = As[k][ty*4+i];
            #pragma unroll
            for (int j = 0; j < 4; j++) bv[j] = Bs[k][tx*4+j];
            #pragma unroll
            for (int i = 0; i < 4; i++)
                #pragma unroll
                for (int j = 0; j < 4; j++)
                    acc[i][j] = fmaf(av[i], bv[j], acc[i][j]);
        }
        __syncthreads();
    }
    #pragma unroll
    for (int i = 0; i < 4; i++) {
        int row = by*64 + ty*4 + i;
        #pragma unroll
        for (int j = 0; j < 4; j++) {
            int col = bx*64 + tx*4 + j;
            float v = acc[i][j];
            if (bias) v += bias[col];
            if (res)  v += res[(size_t)row*N + col];
            C[(size_t)row*N + col] = v;
        }
    }
}

// ---------------- LayerNorm (row of 512) ----------------
__global__ __launch_bounds__(256) void ln_kernel(
    const float* __restrict__ x, const float* __restrict__ g,
    const float* __restrict__ b, float* __restrict__ y)
{
    int row = blockIdx.x;
    const float* xr = x + (size_t)row*DIMM;
    int tid = threadIdx.x;
    float v0 = xr[tid], v1 = xr[tid+256];
    __shared__ float red[8];
    float s = v0 + v1;
    #pragma unroll
    for (int o = 16; o > 0; o >>= 1) s += __shfl_xor_sync(0xffffffffu, s, o);
    if ((tid & 31) == 0) red[tid >> 5] = s;
    __syncthreads();
    float tot = 0.f;
    #pragma unroll
    for (int i = 0; i < 8; i++) tot += red[i];
    float mu = tot * (1.f/512.f);
    float d0 = v0 - mu, d1 = v1 - mu;
    __syncthreads();
    float vs = d0*d0 + d1*d1;
    #pragma unroll
    for (int o = 16; o > 0; o >>= 1) vs += __shfl_xor_sync(0xffffffffu, vs, o);
    if ((tid & 31) == 0) red[tid >> 5] = vs;
    __syncthreads();
    float vtot = 0.f;
    #pragma unroll
    for (int i = 0; i < 8; i++) vtot += red[i];
    float rstd = rsqrtf(vtot * (1.f/512.f) + 1e-5f);
    y[(size_t)row*DIMM + tid]       = d0*rstd*g[tid]       + b[tid];
    y[(size_t)row*DIMM + tid + 256] = d1*rstd*g[tid+256]   + b[tid+256];
}

// ---------------- temporal attention (fused, seq=16) ----------------
// grid (NNS, NHEADS, BB), 256 threads
__global__ __launch_bounds__(256) void attn_time_kernel() {
    int n = blockIdx.x, h = blockIdx.y, b = blockIdx.z;
    __shared__ float qs[16*65], ks[16*65], vs[16*65], ps[16*17];
    int tid = threadIdx.x;
    for (int idx = tid; idx < 16*64; idx += 256) {
        int f = idx >> 6, d = idx & 63;
        size_t base = ((size_t)((b*FFR+f)*NNS + n))*(3*DIMM) + h*DHH + d;
        qs[f*65+d] = g_qkv[base] * QSCALE;
        ks[f*65+d] = g_qkv[base + DIMM];
        vs[f*65+d] = g_qkv[base + 2*DIMM];
    }
    __syncthreads();
    for (int p = tid; p < 16*32; p += 256) {
        int f = p >> 5, d = (p & 31) * 2;
        float s0 = g_fsin[f*64+d],   c0 = g_fcos[f*64+d];
        float s1 = g_fsin[f*64+d+1], c1 = g_fcos[f*64+d+1];
        float q0 = qs[f*65+d], q1 = qs[f*65+d+1];
        qs[f*65+d]   = q0*c0 - q1*s0;
        qs[f*65+d+1] = q1*c1 + q0*s1;
        float k0 = ks[f*65+d], k1 = ks[f*65+d+1];
        ks[f*65+d]   = k0*c0 - k1*s0;
        ks[f*65+d+1] = k1*c1 + k0*s1;
    }
    __syncthreads();
    {
        int i = tid >> 4, j = tid & 15;
        float acc = 0.f;
        #pragma unroll
        for (int d = 0; d < 64; d++) acc += qs[i*65+d]*ks[j*65+d];
        ps[i*17+j] = acc;
    }
    __syncthreads();
    if (tid < 16) {
        float m = -1e30f;
        #pragma unroll
        for (int j = 0; j < 16; j++) m = fmaxf(m, ps[tid*17+j]);
        float s = 0.f;
        #pragma unroll
        for (int j = 0; j < 16; j++) { float e = expf(ps[tid*17+j]-m); ps[tid*17+j]=e; s+=e; }
        float inv = 1.f/s;
        #pragma unroll
        for (int j = 0; j < 16; j++) ps[tid*17+j] *= inv;
    }
    __syncthreads();
    #pragma unroll
    for (int r = 0; r < 4; r++) {
        int idx = tid + r*256;
        int i = idx >> 6, d = idx & 63;
        float acc = 0.f;
        #pragma unroll
        for (int j = 0; j < 16; j++) acc += ps[i*17+j]*vs[j*65+d];
        g_attn[ ((size_t)((b*FFR+i)*NNS + n))*DIMM + h*DHH + d ] = acc;
    }
}

// ---------------- spatial attention: sim = rope(q)·rope(k) ----------------
// grid (6 jtiles, 6 itiles, 512 seqs), seq = (b*8+h)*16+f
__global__ __launch_bounds__(256) void sim_space_kernel() {
    int tj = blockIdx.x, ti = blockIdx.y, seq = blockIdx.z;
    int f = seq & 15; int bh = seq >> 4; int h = bh & 7; int b = bh >> 3;
    __shared__ float qs[32*65], ks[32*65];
    int tid = threadIdx.x;
    for (int idx = tid; idx < 32*64; idx += 256) {
        int r = idx >> 6, d = idx & 63;
        int nq = ti*32 + r, nk = tj*32 + r;
        size_t tq = ((size_t)((b*FFR+f)*NNS + nq))*(3*DIMM) + h*DHH + d;
        size_t tk = ((size_t)((b*FFR+f)*NNS + nk))*(3*DIMM) + DIMM + h*DHH + d;
        qs[r*65+d] = g_qkv[tq] * QSCALE;
        ks[r*65+d] = g_qkv[tk];
    }
    __syncthreads();
    for (int p = tid; p < 32*32; p += 256) {
        int r = p >> 5, d = (p & 31) * 2;
        int nq = ti*32 + r, nk = tj*32 + r;
        {
            float s0 = g_isin[nq*64+d],   c0 = g_icos[nq*64+d];
            float s1 = g_isin[nq*64+d+1], c1 = g_icos[nq*64+d+1];
            float q0 = qs[r*65+d], q1 = qs[r*65+d+1];
            qs[r*65+d]   = q0*c0 - q1*s0;
            qs[r*65+d+1] = q1*c1 + q0*s1;
        }
        {
            float s0 = g_isin[nk*64+d],   c0 = g_icos[nk*64+d];
            float s1 = g_isin[nk*64+d+1], c1 = g_icos[nk*64+d+1];
            float k0 = ks[r*65+d], k1 = ks[r*65+d+1];
            ks[r*65+d]   = k0*c0 - k1*s0;
            ks[r*65+d+1] = k1*c1 + k0*s1;
        }
    }
    __syncthreads();
    int j = tid & 31;
    int i0 = (tid >> 5) * 4;
    float acc[4] = {0.f,0.f,0.f,0.f};
    #pragma unroll
    for (int d = 0; d < 64; d++) {
        float kv = ks[j*65+d];
        #pragma unroll
        for (int r = 0; r < 4; r++) acc[r] += qs[(i0+r)*65+d]*kv;
    }
    size_t base = ((size_t)seq*NNS + ti*32 + i0)*NNS + tj*32 + j;
    #pragma unroll
    for (int r = 0; r < 4; r++) g_sim[base + (size_t)r*NNS] = acc[r];
}

// ---------------- softmax over 192 (warp per row) ----------------
__global__ __launch_bounds__(256) void softmax192_kernel() {
    int row = blockIdx.x*8 + (threadIdx.x >> 5);
    int lane = threadIdx.x & 31;
    float* p = g_sim + (size_t)row*NNS;
    float v[6];
    float m = -1e30f;
    #pragma unroll
    for (int t = 0; t < 6; t++) { v[t] = p[lane + t*32]; m = fmaxf(m, v[t]); }
    #pragma unroll
    for (int o = 16; o > 0; o >>= 1) m = fmaxf(m, __shfl_xor_sync(0xffffffffu, m, o));
    float s = 0.f;
    #pragma unroll
    for (int t = 0; t < 6; t++) { v[t] = expf(v[t]-m); s += v[t]; }
    #pragma unroll
    for (int o = 16; o > 0; o >>= 1) s += __shfl_xor_sync(0xffffffffu, s, o);
    float inv = 1.f/s;
    #pragma unroll
    for (int t = 0; t < 6; t++) p[lane + t*32] = v[t]*inv;
}

// ---------------- spatial attention: O = P @ V (merged-head writeback) ----------------
// grid (6 itiles, 512 seqs)
__global__ __launch_bounds__(256) void av_space_kernel() {
    int ti = blockIdx.x, seq = blockIdx.y;
    int f = seq & 15, h = (seq >> 4) & 7, b = seq >> 7;
    __shared__ float As[32*33], Vs[32*64];
    int tid = threadIdx.x;
    int d = tid & 63, ig = tid >> 6;     // ig 0..3
    float acc[8] = {0.f,0.f,0.f,0.f,0.f,0.f,0.f,0.f};
    for (int jt = 0; jt < 6; jt++) {
        for (int idx = tid; idx < 32*32; idx += 256) {
            int r = idx >> 5, c2 = idx & 31;
            As[r*33+c2] = g_sim[ ((size_t)seq*NNS + ti*32 + r)*NNS + jt*32 + c2 ];
        }
        for (int idx = tid; idx < 32*64; idx += 256) {
            int r = idx >> 6, dd = idx & 63;
            int nk = jt*32 + r;
            Vs[r*64+dd] = g_qkv[ ((size_t)((b*FFR+f)*NNS + nk))*(3*DIMM) + 2*DIMM + h*DHH + dd ];
        }
        __syncthreads();
        #pragma unroll
        for (int jj = 0; jj < 32; jj++) {
            float vv = Vs[jj*64+d];
            #pragma unroll
            for (int r8 = 0; r8 < 8; r8++)
                acc[r8] = fmaf(As[(ig*8+r8)*33+jj], vv, acc[r8]);
        }
        __syncthreads();
    }
    #pragma unroll
    for (int r8 = 0; r8 < 8; r8++) {
        int i = ti*32 + ig*8 + r8;
        g_attn[ ((size_t)((b*FFR+f)*NNS + i))*DIMM + h*DHH + d ] = acc[r8];
    }
}

// ---------------- FFN gate: a * gelu(g) ----------------
__global__ void gate_kernel() {
    int idx = blockIdx.x*blockDim.x + threadIdx.x;
    if (idx >= TT*FFHID) return;
    int t = idx / FFHID, j = idx % FFHID;
    float a = g_h1[(size_t)t*2*FFHID + j];
    float g = g_h1[(size_t)t*2*FFHID + FFHID + j];
    float ge = 0.5f*g*(1.f + erff(g*0.70710678118654752f));
    g_gate[idx] = a*ge;
}

// ---------------- final copy ----------------
__global__ void copy_kernel(float* __restrict__ out) {
    int idx = blockIdx.x*blockDim.x + threadIdx.x;
    if (idx < TT*DIMM) out[idx] = g_x[idx];
}

// ---------------- host orchestration ----------------
extern "C" void kernel_launch(void* const* d_in, const int* in_sizes, int n_in,
                              void* d_out, int out_size) {
    const float* video   = (const float*)d_in[0];
    const float* patch_w = (const float*)d_in[1];
    const float* patch_b = (const float*)d_in[2];
    const float* ln_t_g  = (const float*)d_in[3];
    const float* ln_t_b  = (const float*)d_in[4];
    const float* ln_s_g  = (const float*)d_in[5];
    const float* ln_s_b  = (const float*)d_in[6];
    const float* ln_f_g  = (const float*)d_in[7];
    const float* ln_f_b  = (const float*)d_in[8];
    const float* qkv_t   = (const float*)d_in[9];
    const float* out_t_w = (const float*)d_in[10];
    const float* out_t_b = (const float*)d_in[11];
    const float* qkv_s   = (const float*)d_in[12];
    const float* out_s_w = (const float*)d_in[13];
    const float* out_s_b = (const float*)d_in[14];
    const float* ff_w1   = (const float*)d_in[15];
    const float* ff_b1   = (const float*)d_in[16];
    const float* ff_w2   = (const float*)d_in[17];
    const float* ff_b2   = (const float*)d_in[18];

    float *px, *py, *pqkv, *pattn, *ph1, *pgate, *ppatch;
    cudaGetSymbolAddress((void**)&px,     g_x);
    cudaGetSymbolAddress((void**)&py,     g_y);
    cudaGetSymbolAddress((void**)&pqkv,   g_qkv);
    cudaGetSymbolAddress((void**)&pattn,  g_attn);
    cudaGetSymbolAddress((void**)&ph1,    g_h1);
    cudaGetSymbolAddress((void**)&pgate,  g_gate);
    cudaGetSymbolAddress((void**)&ppatch, g_patch);

    rope_frame_kernel<<<1, 1024>>>();
    rope_image_kernel<<<(NNS*DHH+255)/256, 256>>>();
    patchify_kernel<<<(TT*PATCH_K+255)/256, 256>>>(video);

    // x = patch @ patch_w + patch_b
    sgemm_kernel<<<dim3(DIMM/64, TT/64), 256>>>(ppatch, patch_w, patch_b, nullptr, px,
                                                TT, DIMM, PATCH_K);

    for (int l = 0; l < NDEPTH; l++) {
        // ---- temporal attention ----
        ln_kernel<<<TT, 256>>>(px, ln_t_g + l*DIMM, ln_t_b + l*DIMM, py);
        sgemm_kernel<<<dim3(3*DIMM/64, TT/64), 256>>>(py, qkv_t + (size_t)l*DIMM*3*DIMM,
                                                      nullptr, nullptr, pqkv, TT, 3*DIMM, DIMM);
        attn_time_kernel<<<dim3(NNS, NHEADS, BB), 256>>>();
        sgemm_kernel<<<dim3(DIMM/64, TT/64), 256>>>(pattn, out_t_w + (size_t)l*DIMM*DIMM,
                                                    out_t_b + l*DIMM, px, px, TT, DIMM, DIMM);
        // ---- spatial attention ----
        ln_kernel<<<TT, 256>>>(px, ln_s_g + l*DIMM, ln_s_b + l*DIMM, py);
        sgemm_kernel<<<dim3(3*DIMM/64, TT/64), 256>>>(py, qkv_s + (size_t)l*DIMM*3*DIMM,
                                                      nullptr, nullptr, pqkv, TT, 3*DIMM, DIMM);
        sim_space_kernel<<<dim3(6, 6, BB*NHEADS*FFR), 256>>>();
        softmax192_kernel<<<(BB*NHEADS*FFR*NNS)/8, 256>>>();
        av_space_kernel<<<dim3(6, BB*NHEADS*FFR), 256>>>();
        sgemm_kernel<<<dim3(DIMM/64, TT/64), 256>>>(pattn, out_s_w + (size_t)l*DIMM*DIMM,
                                                    out_s_b + l*DIMM, px, px, TT, DIMM, DIMM);
        // ---- FFN (gated GELU) ----
        ln_kernel<<<TT, 256>>>(px, ln_f_g + l*DIMM, ln_f_b + l*DIMM, py);
        sgemm_kernel<<<dim3(2*FFHID/64, TT/64), 256>>>(py, ff_w1 + (size_t)l*DIMM*2*FFHID,
                                                       ff_b1 + (size_t)l*2*FFHID, nullptr, ph1,
                                                       TT, 2*FFHID, DIMM);
        gate_kernel<<<(TT*FFHID+255)/256, 256>>>();
        sgemm_kernel<<<dim3(DIMM/64, TT/64), 256>>>(pgate, ff_w2 + (size_t)l*FFHID*DIMM,
                                                    ff_b2 + l*DIMM, px, px, TT, DIMM, FFHID);
    }

    copy_kernel<<<(TT*DIMM+255)/256, 256>>>((float*)d_out);
}

// round 2
// speedup vs baseline: 1.1591x; 1.1591x over previous
#include <cuda_runtime.h>
#include <math.h>

// ---------------- problem constants ----------------
#define BB 4
#define FFR 16          // frames
#define CC 3
#define HH 96
#define WW 128
#define PATP 8
#define HPP 12
#define WPP 16
#define NNS 192         // HPP*WPP tokens per frame
#define TT (BB*FFR*NNS) // 12288 total tokens
#define DIMM 512
#define NHEADS 8
#define DHH 64
#define NDEPTH 4
#define FFHID 2048
#define PATCH_K (PATP*PATP*CC) // 192
#define QSCALE 0.125f          // 64^-0.5

// ---------------- device scratch (no allocation allowed) ----------------
__device__ float g_x[TT*DIMM];
__device__ float g_y[TT*DIMM];
__device__ float g_qkv[(size_t)TT*3*DIMM];
__device__ float g_attn[TT*DIMM];
__device__ float g_h1[(size_t)TT*2*FFHID];
__device__ float g_gate[(size_t)TT*FFHID];
__device__ float g_sim[(size_t)BB*NHEADS*FFR*NNS*NNS];
__device__ float g_patch[(size_t)TT*PATCH_K];
__device__ float g_fsin[FFR*DHH], g_fcos[FFR*DHH];
__device__ float g_isin[NNS*DHH], g_icos[NNS*DHH];

// ---------------- rope tables ----------------
__global__ void rope_frame_kernel() {
    int idx = blockIdx.x*blockDim.x + threadIdx.x;
    if (idx >= FFR*DHH) return;
    int f = idx / DHH, j = idx % DHH;
    int i = j & 31;
    float inv = expf(-((float)(2*i)/64.f) * logf(10000.f));
    float a = (float)f * inv;
    g_fsin[idx] = sinf(a);
    g_fcos[idx] = cosf(a);
}

__global__ void rope_image_kernel() {
    int idx = blockIdx.x*blockDim.x + threadIdx.x;
    if (idx >= NNS*DHH) return;
    int n = idx / DHH, j = idx % DHH;
    int half = j >> 1;
    int hp = n / WPP, wp = n % WPP;
    const float PI = 3.14159265358979323846f;
    const float LOG2_5 = 2.3219280948873623f;
    float ang;
    if (half < 16) {
        float sc = exp2f((float)half * (LOG2_5/15.f));
        float hl = -1.f + 2.f*(float)hp/11.f;
        ang = hl * sc * PI;
    } else {
        float sc = exp2f((float)(half-16) * (LOG2_5/15.f));
        float wl = -1.f + 2.f*(float)wp/15.f;
        ang = wl * sc * PI;
    }
    g_isin[idx] = sinf(ang);
    g_icos[idx] = cosf(ang);
}

// ---------------- patchify rearrange ----------------
__global__ void patchify_kernel(const float* __restrict__ video) {
    int idx = blockIdx.x*blockDim.x + threadIdx.x;
    if (idx >= TT*PATCH_K) return;
    int t = idx / PATCH_K, k = idx % PATCH_K;
    int n = t % NNS;
    int bf = t / NNS;
    int hp = n / WPP, wp = n % WPP;
    int p1 = k / (PATP*CC);
    int rem = k % (PATP*CC);
    int p2 = rem / CC;
    int c = rem % CC;
    g_patch[idx] = video[ (((size_t)(bf*CC + c))*HH + hp*PATP + p1)*WW + wp*PATP + p2 ];
}

// ---------------- SGEMM 128x128x16, 8x8/thread, double-buffered ----------------
// C(MxN) = A(MxK) @ B(KxN) [+bias][+res]
__global__ __launch_bounds__(256) void sgemm128_kernel(
    const float* __restrict__ A, const float* __restrict__ B,
    const float* __restrict__ bias, const float* __restrict__ res,
    float* __restrict__ C, int M, int N, int K)
{
    __shared__ float As[2][16][132];   // k-major, m contiguous, padded
    __shared__ float Bs[2][16][128];

    int bx = blockIdx.x, by = blockIdx.y;
    int tid = threadIdx.x;
    int tx = tid & 15, ty = tid >> 4;

    const float* Ap = A + (size_t)(by*128)*K;
    const float* Bp = B + bx*128;

    int arow = tid >> 2;          // 0..63
    int acol = (tid & 3) << 2;    // 0,4,8,12
    int brow = tid >> 4;          // 0..15
    int bcol = (tid & 15) << 2;   // 0..60

    float acc[8][8] = {};
    int KT = K >> 4;

    // preload tile 0
    float4 a0 = *reinterpret_cast<const float4*>(Ap + (size_t)arow*K + acol);
    float4 a1 = *reinterpret_cast<const float4*>(Ap + (size_t)(arow+64)*K + acol);
    float4 b0 = *reinterpret_cast<const float4*>(Bp + (size_t)brow*N + bcol);
    float4 b1 = *reinterpret_cast<const float4*>(Bp + (size_t)brow*N + bcol + 64);

    As[0][acol+0][arow] = a0.x; As[0][acol+1][arow] = a0.y;
    As[0][acol+2][arow] = a0.z; As[0][acol+3][arow] = a0.w;
    As[0][acol+0][arow+64] = a1.x; As[0][acol+1][arow+64] = a1.y;
    As[0][acol+2][arow+64] = a1.z; As[0][acol+3][arow+64] = a1.w;
    *reinterpret_cast<float4*>(&Bs[0][brow][bcol])      = b0;
    *reinterpret_cast<float4*>(&Bs[0][brow][bcol + 64]) = b1;
    __syncthreads();

    int buf = 0;
    for (int kt = 0; kt < KT; kt++) {
        float4 na0, na1, nb0, nb1;
        if (kt + 1 < KT) {
            const float* Ak = Ap + (kt+1)*16;
            na0 = *reinterpret_cast<const float4*>(Ak + (size_t)arow*K + acol);
            na1 = *reinterpret_cast<const float4*>(Ak + (size_t)(arow+64)*K + acol);
            const float* Bk = Bp + (size_t)((kt+1)*16)*N;
            nb0 = *reinterpret_cast<const float4*>(Bk + (size_t)brow*N + bcol);
            nb1 = *reinterpret_cast<const float4*>(Bk + (size_t)brow*N + bcol + 64);
        }
        #pragma unroll
        for (int k = 0; k < 16; k++) {
            float av[8], bv[8];
            *reinterpret_cast<float4*>(av)   = *reinterpret_cast<const float4*>(&As[buf][k][ty*8]);
            *reinterpret_cast<float4*>(av+4) = *reinterpret_cast<const float4*>(&As[buf][k][ty*8+4]);
            *reinterpret_cast<float4*>(bv)   = *reinterpret_cast<const float4*>(&Bs[buf][k][tx*8]);
            *reinterpret_cast<float4*>(bv+4) = *reinterpret_cast<const float4*>(&Bs[buf][k][tx*8+4]);
            #pragma unroll
            for (int i = 0; i < 8; i++)
                #pragma unroll
                for (int j = 0; j < 8; j++)
                    acc[i][j] = fmaf(av[i], bv[j], acc[i][j]);
        }
        if (kt + 1 < KT) {
            int nb = buf ^ 1;
            As[nb][acol+0][arow] = na0.x; As[nb][acol+1][arow] = na0.y;
            As[nb][acol+2][arow] = na0.z; As[nb][acol+3][arow] = na0.w;
            As[nb][acol+0][arow+64] = na1.x; As[nb][acol+1][arow+64] = na1.y;
            As[nb][acol+2][arow+64] = na1.z; As[nb][acol+3][arow+64] = na1.w;
            *reinterpret_cast<float4*>(&Bs[nb][brow][bcol])      = nb0;
            *reinterpret_cast<float4*>(&Bs[nb][brow][bcol + 64]) = nb1;
            __syncthreads();
            buf = nb;
        }
    }

    // epilogue
    #pragma unroll
    for (int i = 0; i < 8; i++) {
        int row = by*128 + ty*8 + i;
        #pragma unroll
        for (int jq = 0; jq < 2; jq++) {
            int col = bx*128 + tx*8 + jq*4;
            float4 v;
            v.x = acc[i][jq*4+0]; v.y = acc[i][jq*4+1];
            v.z = acc[i][jq*4+2]; v.w = acc[i][jq*4+3];
            if (bias) {
                float4 bb = *reinterpret_cast<const float4*>(bias + col);
                v.x += bb.x; v.y += bb.y; v.z += bb.z; v.w += bb.w;
            }
            if (res) {
                float4 rr = *reinterpret_cast<const float4*>(res + (size_t)row*N + col);
                v.x += rr.x; v.y += rr.y; v.z += rr.z; v.w += rr.w;
            }
            *reinterpret_cast<float4*>(C + (size_t)row*N + col) = v;
        }
    }
}

// ---------------- LayerNorm (row of 512) ----------------
__global__ __launch_bounds__(256) void ln_kernel(
    const float* __restrict__ x, const float* __restrict__ g,
    const float* __restrict__ b, float* __restrict__ y)
{
    int row = blockIdx.x;
    const float* xr = x + (size_t)row*DIMM;
    int tid = threadIdx.x;
    float v0 = xr[tid], v1 = xr[tid+256];
    __shared__ float red[8];
    float s = v0 + v1;
    #pragma unroll
    for (int o = 16; o > 0; o >>= 1) s += __shfl_xor_sync(0xffffffffu, s, o);
    if ((tid & 31) == 0) red[tid >> 5] = s;
    __syncthreads();
    float tot = 0.f;
    #pragma unroll
    for (int i = 0; i < 8; i++) tot += red[i];
    float mu = tot * (1.f/512.f);
    float d0 = v0 - mu, d1 = v1 - mu;
    __syncthreads();
    float vs = d0*d0 + d1*d1;
    #pragma unroll
    for (int o = 16; o > 0; o >>= 1) vs += __shfl_xor_sync(0xffffffffu, vs, o);
    if ((tid & 31) == 0) red[tid >> 5] = vs;
    __syncthreads();
    float vtot = 0.f;
    #pragma unroll
    for (int i = 0; i < 8; i++) vtot += red[i];
    float rstd = rsqrtf(vtot * (1.f/512.f) + 1e-5f);
    y[(size_t)row*DIMM + tid]       = d0*rstd*g[tid]       + b[tid];
    y[(size_t)row*DIMM + tid + 256] = d1*rstd*g[tid+256]   + b[tid+256];
}

// ---------------- temporal attention (fused, seq=16) ----------------
__global__ __launch_bounds__(256) void attn_time_kernel() {
    int n = blockIdx.x, h = blockIdx.y, b = blockIdx.z;
    __shared__ float qs[16*65], ks[16*65], vs[16*65], ps[16*17];
    int tid = threadIdx.x;
    for (int idx = tid; idx < 16*64; idx += 256) {
        int f = idx >> 6, d = idx & 63;
        size_t base = ((size_t)((b*FFR+f)*NNS + n))*(3*DIMM) + h*DHH + d;
        qs[f*65+d] = g_qkv[base] * QSCALE;
        ks[f*65+d] = g_qkv[base + DIMM];
        vs[f*65+d] = g_qkv[base + 2*DIMM];
    }
    __syncthreads();
    for (int p = tid; p < 16*32; p += 256) {
        int f = p >> 5, d = (p & 31) * 2;
        float s0 = g_fsin[f*64+d],   c0 = g_fcos[f*64+d];
        float s1 = g_fsin[f*64+d+1], c1 = g_fcos[f*64+d+1];
        float q0 = qs[f*65+d], q1 = qs[f*65+d+1];
        qs[f*65+d]   = q0*c0 - q1*s0;
        qs[f*65+d+1] = q1*c1 + q0*s1;
        float k0 = ks[f*65+d], k1 = ks[f*65+d+1];
        ks[f*65+d]   = k0*c0 - k1*s0;
        ks[f*65+d+1] = k1*c1 + k0*s1;
    }
    __syncthreads();
    {
        int i = tid >> 4, j = tid & 15;
        float acc = 0.f;
        #pragma unroll
        for (int d = 0; d < 64; d++) acc += qs[i*65+d]*ks[j*65+d];
        ps[i*17+j] = acc;
    }
    __syncthreads();
    if (tid < 16) {
        float m = -1e30f;
        #pragma unroll
        for (int j = 0; j < 16; j++) m = fmaxf(m, ps[tid*17+j]);
        float s = 0.f;
        #pragma unroll
        for (int j = 0; j < 16; j++) { float e = expf(ps[tid*17+j]-m); ps[tid*17+j]=e; s+=e; }
        float inv = 1.f/s;
        #pragma unroll
        for (int j = 0; j < 16; j++) ps[tid*17+j] *= inv;
    }
    __syncthreads();
    #pragma unroll
    for (int r = 0; r < 4; r++) {
        int idx = tid + r*256;
        int i = idx >> 6, d = idx & 63;
        float acc = 0.f;
        #pragma unroll
        for (int j = 0; j < 16; j++) acc += ps[i*17+j]*vs[j*65+d];
        g_attn[ ((size_t)((b*FFR+i)*NNS + n))*DIMM + h*DHH + d ] = acc;
    }
}

// ---------------- spatial attention: sim = rope(q)·rope(k) ----------------
__global__ __launch_bounds__(256) void sim_space_kernel() {
    int tj = blockIdx.x, ti = blockIdx.y, seq = blockIdx.z;
    int f = seq & 15; int bh = seq >> 4; int h = bh & 7; int b = bh >> 3;
    __shared__ float qs[32*65], ks[32*65];
    int tid = threadIdx.x;
    for (int idx = tid; idx < 32*64; idx += 256) {
        int r = idx >> 6, d = idx & 63;
        int nq = ti*32 + r, nk = tj*32 + r;
        size_t tq = ((size_t)((b*FFR+f)*NNS + nq))*(3*DIMM) + h*DHH + d;
        size_t tk = ((size_t)((b*FFR+f)*NNS + nk))*(3*DIMM) + DIMM + h*DHH + d;
        qs[r*65+d] = g_qkv[tq] * QSCALE;
        ks[r*65+d] = g_qkv[tk];
    }
    __syncthreads();
    for (int p = tid; p < 32*32; p += 256) {
        int r = p >> 5, d = (p & 31) * 2;
        int nq = ti*32 + r, nk = tj*32 + r;
        {
            float s0 = g_isin[nq*64+d],   c0 = g_icos[nq*64+d];
            float s1 = g_isin[nq*64+d+1], c1 = g_icos[nq*64+d+1];
            float q0 = qs[r*65+d], q1 = qs[r*65+d+1];
            qs[r*65+d]   = q0*c0 - q1*s0;
            qs[r*65+d+1] = q1*c1 + q0*s1;
        }
        {
            float s0 = g_isin[nk*64+d],   c0 = g_icos[nk*64+d];
            float s1 = g_isin[nk*64+d+1], c1 = g_icos[nk*64+d+1];
            float k0 = ks[r*65+d], k1 = ks[r*65+d+1];
            ks[r*65+d]   = k0*c0 - k1*s0;
            ks[r*65+d+1] = k1*c1 + k0*s1;
        }
    }
    __syncthreads();
    int j = tid & 31;
    int i0 = (tid >> 5) * 4;
    float acc[4] = {0.f,0.f,0.f,0.f};
    #pragma unroll
    for (int d = 0; d < 64; d++) {
        float kv = ks[j*65+d];
        #pragma unroll
        for (int r = 0; r < 4; r++) acc[r] += qs[(i0+r)*65+d]*kv;
    }
    size_t base = ((size_t)seq*NNS + ti*32 + i0)*NNS + tj*32 + j;
    #pragma unroll
    for (int r = 0; r < 4; r++) g_sim[base + (size_t)r*NNS] = acc[r];
}

// ---------------- softmax over 192 (warp per row) ----------------
__global__ __launch_bounds__(256) void softmax192_kernel() {
    int row = blockIdx.x*8 + (threadIdx.x >> 5);
    int lane = threadIdx.x & 31;
    float* p = g_sim + (size_t)row*NNS;
    float v[6];
    float m = -1e30f;
    #pragma unroll
    for (int t = 0; t < 6; t++) { v[t] = p[lane + t*32]; m = fmaxf(m, v[t]); }
    #pragma unroll
    for (int o = 16; o > 0; o >>= 1) m = fmaxf(m, __shfl_xor_sync(0xffffffffu, m, o));
    float s = 0.f;
    #pragma unroll
    for (int t = 0; t < 6; t++) { v[t] = expf(v[t]-m); s += v[t]; }
    #pragma unroll
    for (int o = 16; o > 0; o >>= 1) s += __shfl_xor_sync(0xffffffffu, s, o);
    float inv = 1.f/s;
    #pragma unroll
    for (int t = 0; t < 6; t++) p[lane + t*32] = v[t]*inv;
}

// ---------------- spatial attention: O = P @ V ----------------
__global__ __launch_bounds__(256) void av_space_kernel() {
    int ti = blockIdx.x, seq = blockIdx.y;
    int f = seq & 15, h = (seq >> 4) & 7, b = seq >> 7;
    __shared__ float As[32*33], Vs[32*64];
    int tid = threadIdx.x;
    int d = tid & 63, ig = tid >> 6;
    float acc[8] = {0.f,0.f,0.f,0.f,0.f,0.f,0.f,0.f};
    for (int jt = 0; jt < 6; jt++) {
        for (int idx = tid; idx < 32*32; idx += 256) {
            int r = idx >> 5, c2 = idx & 31;
            As[r*33+c2] = g_sim[ ((size_t)seq*NNS + ti*32 + r)*NNS + jt*32 + c2 ];
        }
        for (int idx = tid; idx < 32*64; idx += 256) {
            int r = idx >> 6, dd = idx & 63;
            int nk = jt*32 + r;
            Vs[r*64+dd] = g_qkv[ ((size_t)((b*FFR+f)*NNS + nk))*(3*DIMM) + 2*DIMM + h*DHH + dd ];
        }
        __syncthreads();
        #pragma unroll
        for (int jj = 0; jj < 32; jj++) {
            float vv = Vs[jj*64+d];
            #pragma unroll
            for (int r8 = 0; r8 < 8; r8++)
                acc[r8] = fmaf(As[(ig*8+r8)*33+jj], vv, acc[r8]);
        }
        __syncthreads();
    }
    #pragma unroll
    for (int r8 = 0; r8 < 8; r8++) {
        int i = ti*32 + ig*8 + r8;
        g_attn[ ((size_t)((b*FFR+f)*NNS + i))*DIMM + h*DHH + d ] = acc[r8];
    }
}

// ---------------- FFN gate: a * gelu(g), float4 ----------------
__global__ void gate_kernel() {
    int idx = blockIdx.x*blockDim.x + threadIdx.x;   // in float4 units
    if (idx >= TT*FFHID/4) return;
    int t = idx / (FFHID/4), j4 = idx % (FFHID/4);
    const float4 a = *reinterpret_cast<const float4*>(&g_h1[(size_t)t*2*FFHID + j4*4]);
    const float4 g = *reinterpret_cast<const float4*>(&g_h1[(size_t)t*2*FFHID + FFHID + j4*4]);
    float4 o;
    o.x = a.x * 0.5f*g.x*(1.f + erff(g.x*0.70710678118654752f));
    o.y = a.y * 0.5f*g.y*(1.f + erff(g.y*0.70710678118654752f));
    o.z = a.z * 0.5f*g.z*(1.f + erff(g.z*0.70710678118654752f));
    o.w = a.w * 0.5f*g.w*(1.f + erff(g.w*0.70710678118654752f));
    *reinterpret_cast<float4*>(&g_gate[(size_t)t*FFHID + j4*4]) = o;
}

// ---------------- host orchestration ----------------
extern "C" void kernel_launch(void* const* d_in, const int* in_sizes, int n_in,
                              void* d_out, int out_size) {
    const float* video   = (const float*)d_in[0];
    const float* patch_w = (const float*)d_in[1];
    const float* patch_b = (const float*)d_in[2];
    const float* ln_t_g  = (const float*)d_in[3];
    const float* ln_t_b  = (const float*)d_in[4];
    const float* ln_s_g  = (const float*)d_in[5];
    const float* ln_s_b  = (const float*)d_in[6];
    const float* ln_f_g  = (const float*)d_in[7];
    const float* ln_f_b  = (const float*)d_in[8];
    const float* qkv_t   = (const float*)d_in[9];
    const float* out_t_w = (const float*)d_in[10];
    const float* out_t_b = (const float*)d_in[11];
    const float* qkv_s   = (const float*)d_in[12];
    const float* out_s_w = (const float*)d_in[13];
    const float* out_s_b = (const float*)d_in[14];
    const float* ff_w1   = (const float*)d_in[15];
    const float* ff_b1   = (const float*)d_in[16];
    const float* ff_w2   = (const float*)d_in[17];
    const float* ff_b2   = (const float*)d_in[18];

    float *px, *py, *pqkv, *pattn, *ph1, *pgate, *ppatch;
    cudaGetSymbolAddress((void**)&px,     g_x);
    cudaGetSymbolAddress((void**)&py,     g_y);
    cudaGetSymbolAddress((void**)&pqkv,   g_qkv);
    cudaGetSymbolAddress((void**)&pattn,  g_attn);
    cudaGetSymbolAddress((void**)&ph1,    g_h1);
    cudaGetSymbolAddress((void**)&pgate,  g_gate);
    cudaGetSymbolAddress((void**)&ppatch, g_patch);

    rope_frame_kernel<<<1, 1024>>>();
    rope_image_kernel<<<(NNS*DHH+255)/256, 256>>>();
    patchify_kernel<<<(TT*PATCH_K+255)/256, 256>>>(video);

    // x = patch @ patch_w + patch_b
    sgemm128_kernel<<<dim3(DIMM/128, TT/128), 256>>>(ppatch, patch_w, patch_b, nullptr, px,
                                                     TT, DIMM, PATCH_K);

    for (int l = 0; l < NDEPTH; l++) {
        // ---- temporal attention ----
        ln_kernel<<<TT, 256>>>(px, ln_t_g + l*DIMM, ln_t_b + l*DIMM, py);
        sgemm128_kernel<<<dim3(3*DIMM/128, TT/128), 256>>>(py, qkv_t + (size_t)l*DIMM*3*DIMM,
                                                           nullptr, nullptr, pqkv, TT, 3*DIMM, DIMM);
        attn_time_kernel<<<dim3(NNS, NHEADS, BB), 256>>>();
        sgemm128_kernel<<<dim3(DIMM/128, TT/128), 256>>>(pattn, out_t_w + (size_t)l*DIMM*DIMM,
                                                         out_t_b + l*DIMM, px, px, TT, DIMM, DIMM);
        // ---- spatial attention ----
        ln_kernel<<<TT, 256>>>(px, ln_s_g + l*DIMM, ln_s_b + l*DIMM, py);
        sgemm128_kernel<<<dim3(3*DIMM/128, TT/128), 256>>>(py, qkv_s + (size_t)l*DIMM*3*DIMM,
                                                           nullptr, nullptr, pqkv, TT, 3*DIMM, DIMM);
        sim_space_kernel<<<dim3(6, 6, BB*NHEADS*FFR), 256>>>();
        softmax192_kernel<<<(BB*NHEADS*FFR*NNS)/8, 256>>>();
        av_space_kernel<<<dim3(6, BB*NHEADS*FFR), 256>>>();
        sgemm128_kernel<<<dim3(DIMM/128, TT/128), 256>>>(pattn, out_s_w + (size_t)l*DIMM*DIMM,
                                                         out_s_b + l*DIMM, px, px, TT, DIMM, DIMM);
        // ---- FFN (gated GELU) ----
        ln_kernel<<<TT, 256>>>(px, ln_f_g + l*DIMM, ln_f_b + l*DIMM, py);
        sgemm128_kernel<<<dim3(2*FFHID/128, TT/128), 256>>>(py, ff_w1 + (size_t)l*DIMM*2*FFHID,
                                                            ff_b1 + (size_t)l*2*FFHID, nullptr, ph1,
                                                            TT, 2*FFHID, DIMM);
        gate_kernel<<<(TT*FFHID/4+255)/256, 256>>>();
        // last layer's ff2 writes the final output directly
        float* cdst = (l == NDEPTH-1) ? (float*)d_out : px;
        sgemm128_kernel<<<dim3(DIMM/128, TT/128), 256>>>(pgate, ff_w2 + (size_t)l*FFHID*DIMM,
                                                         ff_b2 + l*DIMM, px, cdst, TT, DIMM, FFHID);
    }
}

// round 3
// speedup vs baseline: 2.2223x; 1.9173x over previous
#include <cuda_runtime.h>
#include <math.h>
#include <stdint.h>

// ---------------- problem constants ----------------
#define BB 4
#define FFR 16
#define CC 3
#define HH 96
#define WW 128
#define PATP 8
#define HPP 12
#define WPP 16
#define NNS 192
#define TT (BB*FFR*NNS) // 12288
#define DIMM 512
#define NHEADS 8
#define DHH 64
#define NDEPTH 4
#define FFHID 2048
#define PATCH_K (PATP*PATP*CC) // 192
#define QSCALE 0.125f

// ---------------- device scratch ----------------
__device__ float g_x[TT*DIMM];
__device__ float g_y[TT*DIMM];
__device__ float g_qkv[(size_t)TT*3*DIMM];
__device__ float g_attn[TT*DIMM];
__device__ float g_h1[(size_t)TT*2*FFHID];
__device__ float g_gate[(size_t)TT*FFHID];
__device__ float g_sim[(size_t)BB*NHEADS*FFR*NNS*NNS];
__device__ float g_patch[(size_t)TT*PATCH_K];
__device__ float g_fsin[FFR*DHH], g_fcos[FFR*DHH];
__device__ float g_isin[NNS*DHH], g_icos[NNS*DHH];

// ---------------- tf32 helpers ----------------
__device__ __forceinline__ float to_tf32(float x) {
    uint32_t u;
    asm("cvt.rna.tf32.f32 %0, %1;" : "=r"(u) : "f"(x));
    return __uint_as_float(u);
}

__device__ __forceinline__ void mma_tf32(float* c, const uint32_t* a, const uint32_t* b) {
    asm volatile(
        "mma.sync.aligned.m16n8k8.row.col.f32.tf32.tf32.f32 "
        "{%0,%1,%2,%3}, {%4,%5,%6,%7}, {%8,%9}, {%0,%1,%2,%3};"
        : "+f"(c[0]), "+f"(c[1]), "+f"(c[2]), "+f"(c[3])
        : "r"(a[0]), "r"(a[1]), "r"(a[2]), "r"(a[3]), "r"(b[0]), "r"(b[1]));
}

// ---------------- rope tables ----------------
__global__ void rope_frame_kernel() {
    int idx = blockIdx.x*blockDim.x + threadIdx.x;
    if (idx >= FFR*DHH) return;
    int f = idx / DHH, j = idx % DHH;
    int i = j & 31;
    float inv = expf(-((float)(2*i)/64.f) * logf(10000.f));
    float a = (float)f * inv;
    g_fsin[idx] = sinf(a);
    g_fcos[idx] = cosf(a);
}

__global__ void rope_image_kernel() {
    int idx = blockIdx.x*blockDim.x + threadIdx.x;
    if (idx >= NNS*DHH) return;
    int n = idx / DHH, j = idx % DHH;
    int half = j >> 1;
    int hp = n / WPP, wp = n % WPP;
    const float PI = 3.14159265358979323846f;
    const float LOG2_5 = 2.3219280948873623f;
    float ang;
    if (half < 16) {
        float sc = exp2f((float)half * (LOG2_5/15.f));
        float hl = -1.f + 2.f*(float)hp/11.f;
        ang = hl * sc * PI;
    } else {
        float sc = exp2f((float)(half-16) * (LOG2_5/15.f));
        float wl = -1.f + 2.f*(float)wp/15.f;
        ang = wl * sc * PI;
    }
    g_isin[idx] = sinf(ang);
    g_icos[idx] = cosf(ang);
}

// ---------------- patchify ----------------
__global__ void patchify_kernel(const float* __restrict__ video) {
    int idx = blockIdx.x*blockDim.x + threadIdx.x;
    if (idx >= TT*PATCH_K) return;
    int t = idx / PATCH_K, k = idx % PATCH_K;
    int n = t % NNS;
    int bf = t / NNS;
    int hp = n / WPP, wp = n % WPP;
    int p1 = k / (PATP*CC);
    int rem = k % (PATP*CC);
    int p2 = rem / CC;
    int c = rem % CC;
    g_patch[idx] = video[ (((size_t)(bf*CC + c))*HH + hp*PATP + p1)*WW + wp*PATP + p2 ];
}

// ---------------- TF32 tensor-core GEMM: 128x128x16, mma.m16n8k8 ----------------
// C(MxN) = A(MxK) @ B(KxN) [+bias][+res]
__global__ __launch_bounds__(256) void tgemm_kernel(
    const float* __restrict__ A, const float* __restrict__ B,
    const float* __restrict__ bias, const float* __restrict__ res,
    float* __restrict__ C, int M, int N, int K)
{
    __shared__ float As[2][16][132];   // [k][m], padded
    __shared__ float Bs[2][16][132];   // [k][n], padded

    int bx = blockIdx.x, by = blockIdx.y;
    int tid = threadIdx.x;
    int lane = tid & 31;
    int grp = lane >> 2, tig = lane & 3;
    int warp = tid >> 5;
    int wm = (warp & 1) * 64;       // warp tile 64x32
    int wn = (warp >> 1) * 32;

    const float* Ap = A + (size_t)(by*128)*K;
    const float* Bp = B + bx*128;

    int arow = tid >> 2;          // 0..63
    int acol = (tid & 3) << 2;    // 0,4,8,12
    int brow = tid >> 4;          // 0..15
    int bcol = (tid & 15) << 2;   // 0..60

    float acc[4][4][4] = {};
    int KT = K >> 4;

    // preload tile 0
    {
        float4 a0 = *reinterpret_cast<const float4*>(Ap + (size_t)arow*K + acol);
        float4 a1 = *reinterpret_cast<const float4*>(Ap + (size_t)(arow+64)*K + acol);
        As[0][acol+0][arow] = to_tf32(a0.x); As[0][acol+1][arow] = to_tf32(a0.y);
        As[0][acol+2][arow] = to_tf32(a0.z); As[0][acol+3][arow] = to_tf32(a0.w);
        As[0][acol+0][arow+64] = to_tf32(a1.x); As[0][acol+1][arow+64] = to_tf32(a1.y);
        As[0][acol+2][arow+64] = to_tf32(a1.z); As[0][acol+3][arow+64] = to_tf32(a1.w);
        float4 b0 = *reinterpret_cast<const float4*>(Bp + (size_t)brow*N + bcol);
        float4 b1 = *reinterpret_cast<const float4*>(Bp + (size_t)brow*N + bcol + 64);
        Bs[0][brow][bcol+0] = to_tf32(b0.x); Bs[0][brow][bcol+1] = to_tf32(b0.y);
        Bs[0][brow][bcol+2] = to_tf32(b0.z); Bs[0][brow][bcol+3] = to_tf32(b0.w);
        Bs[0][brow][bcol+64] = to_tf32(b1.x); Bs[0][brow][bcol+65] = to_tf32(b1.y);
        Bs[0][brow][bcol+66] = to_tf32(b1.z); Bs[0][brow][bcol+67] = to_tf32(b1.w);
    }
    __syncthreads();

    int buf = 0;
    for (int kt = 0; kt < KT; kt++) {
        float4 na0, na1, nb0, nb1;
        if (kt + 1 < KT) {
            const float* Ak = Ap + (kt+1)*16;
            na0 = *reinterpret_cast<const float4*>(Ak + (size_t)arow*K + acol);
            na1 = *reinterpret_cast<const float4*>(Ak + (size_t)(arow+64)*K + acol);
            const float* Bk = Bp + (size_t)((kt+1)*16)*N;
            nb0 = *reinterpret_cast<const float4*>(Bk + (size_t)brow*N + bcol);
            nb1 = *reinterpret_cast<const float4*>(Bk + (size_t)brow*N + bcol + 64);
        }
        #pragma unroll
        for (int ks = 0; ks < 2; ks++) {
            int k0 = ks*8;
            uint32_t af[4][4], bf[4][2];
            #pragma unroll
            for (int mi = 0; mi < 4; mi++) {
                af[mi][0] = __float_as_uint(As[buf][k0+tig  ][wm+mi*16+grp  ]);
                af[mi][1] = __float_as_uint(As[buf][k0+tig  ][wm+mi*16+grp+8]);
                af[mi][2] = __float_as_uint(As[buf][k0+tig+4][wm+mi*16+grp  ]);
                af[mi][3] = __float_as_uint(As[buf][k0+tig+4][wm+mi*16+grp+8]);
            }
            #pragma unroll
            for (int ni = 0; ni < 4; ni++) {
                bf[ni][0] = __float_as_uint(Bs[buf][k0+tig  ][wn+ni*8+grp]);
                bf[ni][1] = __float_as_uint(Bs[buf][k0+tig+4][wn+ni*8+grp]);
            }
            #pragma unroll
            for (int mi = 0; mi < 4; mi++)
                #pragma unroll
                for (int ni = 0; ni < 4; ni++)
                    mma_tf32(acc[mi][ni], af[mi], bf[ni]);
        }
        if (kt + 1 < KT) {
            int nb = buf ^ 1;
            As[nb][acol+0][arow] = to_tf32(na0.x); As[nb][acol+1][arow] = to_tf32(na0.y);
            As[nb][acol+2][arow] = to_tf32(na0.z); As[nb][acol+3][arow] = to_tf32(na0.w);
            As[nb][acol+0][arow+64] = to_tf32(na1.x); As[nb][acol+1][arow+64] = to_tf32(na1.y);
            As[nb][acol+2][arow+64] = to_tf32(na1.z); As[nb][acol+3][arow+64] = to_tf32(na1.w);
            Bs[nb][brow][bcol+0] = to_tf32(nb0.x); Bs[nb][brow][bcol+1] = to_tf32(nb0.y);
            Bs[nb][brow][bcol+2] = to_tf32(nb0.z); Bs[nb][brow][bcol+3] = to_tf32(nb0.w);
            Bs[nb][brow][bcol+64] = to_tf32(nb1.x); Bs[nb][brow][bcol+65] = to_tf32(nb1.y);
            Bs[nb][brow][bcol+66] = to_tf32(nb1.z); Bs[nb][brow][bcol+67] = to_tf32(nb1.w);
            __syncthreads();
            buf = nb;
        }
    }

    // epilogue
    #pragma unroll
    for (int mi = 0; mi < 4; mi++) {
        #pragma unroll
        for (int ni = 0; ni < 4; ni++) {
            int row0 = by*128 + wm + mi*16 + grp;
            int row1 = row0 + 8;
            int col  = bx*128 + wn + ni*8 + 2*tig;
            float2 v0 = make_float2(acc[mi][ni][0], acc[mi][ni][1]);
            float2 v1 = make_float2(acc[mi][ni][2], acc[mi][ni][3]);
            if (bias) {
                float2 bb = *reinterpret_cast<const float2*>(bias + col);
                v0.x += bb.x; v0.y += bb.y; v1.x += bb.x; v1.y += bb.y;
            }
            if (res) {
                float2 r0 = *reinterpret_cast<const float2*>(res + (size_t)row0*N + col);
                float2 r1 = *reinterpret_cast<const float2*>(res + (size_t)row1*N + col);
                v0.x += r0.x; v0.y += r0.y; v1.x += r1.x; v1.y += r1.y;
            }
            *reinterpret_cast<float2*>(C + (size_t)row0*N + col) = v0;
            *reinterpret_cast<float2*>(C + (size_t)row1*N + col) = v1;
        }
    }
}

// ---------------- LayerNorm ----------------
__global__ __launch_bounds__(256) void ln_kernel(
    const float* __restrict__ x, const float* __restrict__ g,
    const float* __restrict__ b, float* __restrict__ y)
{
    int row = blockIdx.x;
    const float* xr = x + (size_t)row*DIMM;
    int tid = threadIdx.x;
    float v0 = xr[tid], v1 = xr[tid+256];
    __shared__ float red[8];
    float s = v0 + v1;
    #pragma unroll
    for (int o = 16; o > 0; o >>= 1) s += __shfl_xor_sync(0xffffffffu, s, o);
    if ((tid & 31) == 0) red[tid >> 5] = s;
    __syncthreads();
    float tot = 0.f;
    #pragma unroll
    for (int i = 0; i < 8; i++) tot += red[i];
    float mu = tot * (1.f/512.f);
    float d0 = v0 - mu, d1 = v1 - mu;
    __syncthreads();
    float vs = d0*d0 + d1*d1;
    #pragma unroll
    for (int o = 16; o > 0; o >>= 1) vs += __shfl_xor_sync(0xffffffffu, vs, o);
    if ((tid & 31) == 0) red[tid >> 5] = vs;
    __syncthreads();
    float vtot = 0.f;
    #pragma unroll
    for (int i = 0; i < 8; i++) vtot += red[i];
    float rstd = rsqrtf(vtot * (1.f/512.f) + 1e-5f);
    y[(size_t)row*DIMM + tid]       = d0*rstd*g[tid]       + b[tid];
    y[(size_t)row*DIMM + tid + 256] = d1*rstd*g[tid+256]   + b[tid+256];
}

// ---------------- temporal attention ----------------
__global__ __launch_bounds__(256) void attn_time_kernel() {
    int n = blockIdx.x, h = blockIdx.y, b = blockIdx.z;
    __shared__ float qs[16*65], ks[16*65], vs[16*65], ps[16*17];
    int tid = threadIdx.x;
    for (int idx = tid; idx < 16*64; idx += 256) {
        int f = idx >> 6, d = idx & 63;
        size_t base = ((size_t)((b*FFR+f)*NNS + n))*(3*DIMM) + h*DHH + d;
        qs[f*65+d] = g_qkv[base] * QSCALE;
        ks[f*65+d] = g_qkv[base + DIMM];
        vs[f*65+d] = g_qkv[base + 2*DIMM];
    }
    __syncthreads();
    for (int p = tid; p < 16*32; p += 256) {
        int f = p >> 5, d = (p & 31) * 2;
        float s0 = g_fsin[f*64+d],   c0 = g_fcos[f*64+d];
        float s1 = g_fsin[f*64+d+1], c1 = g_fcos[f*64+d+1];
        float q0 = qs[f*65+d], q1 = qs[f*65+d+1];
        qs[f*65+d]   = q0*c0 - q1*s0;
        qs[f*65+d+1] = q1*c1 + q0*s1;
        float k0 = ks[f*65+d], k1 = ks[f*65+d+1];
        ks[f*65+d]   = k0*c0 - k1*s0;
        ks[f*65+d+1] = k1*c1 + k0*s1;
    }
    __syncthreads();
    {
        int i = tid >> 4, j = tid & 15;
        float acc = 0.f;
        #pragma unroll
        for (int d = 0; d < 64; d++) acc += qs[i*65+d]*ks[j*65+d];
        ps[i*17+j] = acc;
    }
    __syncthreads();
    if (tid < 16) {
        float m = -1e30f;
        #pragma unroll
        for (int j = 0; j < 16; j++) m = fmaxf(m, ps[tid*17+j]);
        float s = 0.f;
        #pragma unroll
        for (int j = 0; j < 16; j++) { float e = expf(ps[tid*17+j]-m); ps[tid*17+j]=e; s+=e; }
        float inv = 1.f/s;
        #pragma unroll
        for (int j = 0; j < 16; j++) ps[tid*17+j] *= inv;
    }
    __syncthreads();
    #pragma unroll
    for (int r = 0; r < 4; r++) {
        int idx = tid + r*256;
        int i = idx >> 6, d = idx & 63;
        float acc = 0.f;
        #pragma unroll
        for (int j = 0; j < 16; j++) acc += ps[i*17+j]*vs[j*65+d];
        g_attn[ ((size_t)((b*FFR+i)*NNS + n))*DIMM + h*DHH + d ] = acc;
    }
}

// ---------------- spatial attention sim ----------------
__global__ __launch_bounds__(256) void sim_space_kernel() {
    int tj = blockIdx.x, ti = blockIdx.y, seq = blockIdx.z;
    int f = seq & 15; int bh = seq >> 4; int h = bh & 7; int b = bh >> 3;
    __shared__ float qs[32*65], ks[32*65];
    int tid = threadIdx.x;
    for (int idx = tid; idx < 32*64; idx += 256) {
        int r = idx >> 6, d = idx & 63;
        int nq = ti*32 + r, nk = tj*32 + r;
        size_t tq = ((size_t)((b*FFR+f)*NNS + nq))*(3*DIMM) + h*DHH + d;
        size_t tk = ((size_t)((b*FFR+f)*NNS + nk))*(3*DIMM) + DIMM + h*DHH + d;
        qs[r*65+d] = g_qkv[tq] * QSCALE;
        ks[r*65+d] = g_qkv[tk];
    }
    __syncthreads();
    for (int p = tid; p < 32*32; p += 256) {
        int r = p >> 5, d = (p & 31) * 2;
        int nq = ti*32 + r, nk = tj*32 + r;
        {
            float s0 = g_isin[nq*64+d],   c0 = g_icos[nq*64+d];
            float s1 = g_isin[nq*64+d+1], c1 = g_icos[nq*64+d+1];
            float q0 = qs[r*65+d], q1 = qs[r*65+d+1];
            qs[r*65+d]   = q0*c0 - q1*s0;
            qs[r*65+d+1] = q1*c1 + q0*s1;
        }
        {
            float s0 = g_isin[nk*64+d],   c0 = g_icos[nk*64+d];
            float s1 = g_isin[nk*64+d+1], c1 = g_icos[nk*64+d+1];
            float k0 = ks[r*65+d], k1 = ks[r*65+d+1];
            ks[r*65+d]   = k0*c0 - k1*s0;
            ks[r*65+d+1] = k1*c1 + k0*s1;
        }
    }
    __syncthreads();
    int j = tid & 31;
    int i0 = (tid >> 5) * 4;
    float acc[4] = {0.f,0.f,0.f,0.f};
    #pragma unroll
    for (int d = 0; d < 64; d++) {
        float kv = ks[j*65+d];
        #pragma unroll
        for (int r = 0; r < 4; r++) acc[r] += qs[(i0+r)*65+d]*kv;
    }
    size_t base = ((size_t)seq*NNS + ti*32 + i0)*NNS + tj*32 + j;
    #pragma unroll
    for (int r = 0; r < 4; r++) g_sim[base + (size_t)r*NNS] = acc[r];
}

// ---------------- softmax over 192 ----------------
__global__ __launch_bounds__(256) void softmax192_kernel() {
    int row = blockIdx.x*8 + (threadIdx.x >> 5);
    int lane = threadIdx.x & 31;
    float* p = g_sim + (size_t)row*NNS;
    float v[6];
    float m = -1e30f;
    #pragma unroll
    for (int t = 0; t < 6; t++) { v[t] = p[lane + t*32]; m = fmaxf(m, v[t]); }
    #pragma unroll
    for (int o = 16; o > 0; o >>= 1) m = fmaxf(m, __shfl_xor_sync(0xffffffffu, m, o));
    float s = 0.f;
    #pragma unroll
    for (int t = 0; t < 6; t++) { v[t] = expf(v[t]-m); s += v[t]; }
    #pragma unroll
    for (int o = 16; o > 0; o >>= 1) s += __shfl_xor_sync(0xffffffffu, s, o);
    float inv = 1.f/s;
    #pragma unroll
    for (int t = 0; t < 6; t++) p[lane + t*32] = v[t]*inv;
}

// ---------------- spatial attention AV ----------------
__global__ __launch_bounds__(256) void av_space_kernel() {
    int ti = blockIdx.x, seq = blockIdx.y;
    int f = seq & 15, h = (seq >> 4) & 7, b = seq >> 7;
    __shared__ float As2[32*33], Vs[32*64];
    int tid = threadIdx.x;
    int d = tid & 63, ig = tid >> 6;
    float acc[8] = {0.f,0.f,0.f,0.f,0.f,0.f,0.f,0.f};
    for (int jt = 0; jt < 6; jt++) {
        for (int idx = tid; idx < 32*32; idx += 256) {
            int r = idx >> 5, c2 = idx & 31;
            As2[r*33+c2] = g_sim[ ((size_t)seq*NNS + ti*32 + r)*NNS + jt*32 + c2 ];
        }
        for (int idx = tid; idx < 32*64; idx += 256) {
            int r = idx >> 6, dd = idx & 63;
            int nk = jt*32 + r;
            Vs[r*64+dd] = g_qkv[ ((size_t)((b*FFR+f)*NNS + nk))*(3*DIMM) + 2*DIMM + h*DHH + dd ];
        }
        __syncthreads();
        #pragma unroll
        for (int jj = 0; jj < 32; jj++) {
            float vv = Vs[jj*64+d];
            #pragma unroll
            for (int r8 = 0; r8 < 8; r8++)
                acc[r8] = fmaf(As2[(ig*8+r8)*33+jj], vv, acc[r8]);
        }
        __syncthreads();
    }
    #pragma unroll
    for (int r8 = 0; r8 < 8; r8++) {
        int i = ti*32 + ig*8 + r8;
        g_attn[ ((size_t)((b*FFR+f)*NNS + i))*DIMM + h*DHH + d ] = acc[r8];
    }
}

// ---------------- FFN gate ----------------
__global__ void gate_kernel() {
    int idx = blockIdx.x*blockDim.x + threadIdx.x;
    if (idx >= TT*FFHID/4) return;
    int t = idx / (FFHID/4), j4 = idx % (FFHID/4);
    const float4 a = *reinterpret_cast<const float4*>(&g_h1[(size_t)t*2*FFHID + j4*4]);
    const float4 g = *reinterpret_cast<const float4*>(&g_h1[(size_t)t*2*FFHID + FFHID + j4*4]);
    float4 o;
    o.x = a.x * 0.5f*g.x*(1.f + erff(g.x*0.70710678118654752f));
    o.y = a.y * 0.5f*g.y*(1.f + erff(g.y*0.70710678118654752f));
    o.z = a.z * 0.5f*g.z*(1.f + erff(g.z*0.70710678118654752f));
    o.w = a.w * 0.5f*g.w*(1.f + erff(g.w*0.70710678118654752f));
    *reinterpret_cast<float4*>(&g_gate[(size_t)t*FFHID + j4*4]) = o;
}

// ---------------- host orchestration ----------------
extern "C" void kernel_launch(void* const* d_in, const int* in_sizes, int n_in,
                              void* d_out, int out_size) {
    const float* video   = (const float*)d_in[0];
    const float* patch_w = (const float*)d_in[1];
    const float* patch_b = (const float*)d_in[2];
    const float* ln_t_g  = (const float*)d_in[3];
    const float* ln_t_b  = (const float*)d_in[4];
    const float* ln_s_g  = (const float*)d_in[5];
    const float* ln_s_b  = (const float*)d_in[6];
    const float* ln_f_g  = (const float*)d_in[7];
    const float* ln_f_b  = (const float*)d_in[8];
    const float* qkv_t   = (const float*)d_in[9];
    const float* out_t_w = (const float*)d_in[10];
    const float* out_t_b = (const float*)d_in[11];
    const float* qkv_s   = (const float*)d_in[12];
    const float* out_s_w = (const float*)d_in[13];
    const float* out_s_b = (const float*)d_in[14];
    const float* ff_w1   = (const float*)d_in[15];
    const float* ff_b1   = (const float*)d_in[16];
    const float* ff_w2   = (const float*)d_in[17];
    const float* ff_b2   = (const float*)d_in[18];

    float *px, *py, *pqkv, *pattn, *ph1, *pgate, *ppatch;
    cudaGetSymbolAddress((void**)&px,     g_x);
    cudaGetSymbolAddress((void**)&py,     g_y);
    cudaGetSymbolAddress((void**)&pqkv,   g_qkv);
    cudaGetSymbolAddress((void**)&pattn,  g_attn);
    cudaGetSymbolAddress((void**)&ph1,    g_h1);
    cudaGetSymbolAddress((void**)&pgate,  g_gate);
    cudaGetSymbolAddress((void**)&ppatch, g_patch);

    rope_frame_kernel<<<1, 1024>>>();
    rope_image_kernel<<<(NNS*DHH+255)/256, 256>>>();
    patchify_kernel<<<(TT*PATCH_K+255)/256, 256>>>(video);

    tgemm_kernel<<<dim3(DIMM/128, TT/128), 256>>>(ppatch, patch_w, patch_b, nullptr, px,
                                                  TT, DIMM, PATCH_K);

    for (int l = 0; l < NDEPTH; l++) {
        // ---- temporal attention ----
        ln_kernel<<<TT, 256>>>(px, ln_t_g + l*DIMM, ln_t_b + l*DIMM, py);
        tgemm_kernel<<<dim3(3*DIMM/128, TT/128), 256>>>(py, qkv_t + (size_t)l*DIMM*3*DIMM,
                                                        nullptr, nullptr, pqkv, TT, 3*DIMM, DIMM);
        attn_time_kernel<<<dim3(NNS, NHEADS, BB), 256>>>();
        tgemm_kernel<<<dim3(DIMM/128, TT/128), 256>>>(pattn, out_t_w + (size_t)l*DIMM*DIMM,
                                                      out_t_b + l*DIMM, px, px, TT, DIMM, DIMM);
        // ---- spatial attention ----
        ln_kernel<<<TT, 256>>>(px, ln_s_g + l*DIMM, ln_s_b + l*DIMM, py);
        tgemm_kernel<<<dim3(3*DIMM/128, TT/128), 256>>>(py, qkv_s + (size_t)l*DIMM*3*DIMM,
                                                        nullptr, nullptr, pqkv, TT, 3*DIMM, DIMM);
        sim_space_kernel<<<dim3(6, 6, BB*NHEADS*FFR), 256>>>();
        softmax192_kernel<<<(BB*NHEADS*FFR*NNS)/8, 256>>>();
        av_space_kernel<<<dim3(6, BB*NHEADS*FFR), 256>>>();
        tgemm_kernel<<<dim3(DIMM/128, TT/128), 256>>>(pattn, out_s_w + (size_t)l*DIMM*DIMM,
                                                      out_s_b + l*DIMM, px, px, TT, DIMM, DIMM);
        // ---- FFN ----
        ln_kernel<<<TT, 256>>>(px, ln_f_g + l*DIMM, ln_f_b + l*DIMM, py);
        tgemm_kernel<<<dim3(2*FFHID/128, TT/128), 256>>>(py, ff_w1 + (size_t)l*DIMM*2*FFHID,
                                                         ff_b1 + (size_t)l*2*FFHID, nullptr, ph1,
                                                         TT, 2*FFHID, DIMM);
        gate_kernel<<<(TT*FFHID/4+255)/256, 256>>>();
        float* cdst = (l == NDEPTH-1) ? (float*)d_out : px;
        tgemm_kernel<<<dim3(DIMM/128, TT/128), 256>>>(pgate, ff_w2 + (size_t)l*FFHID*DIMM,
                                                      ff_b2 + l*DIMM, px, cdst, TT, DIMM, FFHID);
    }
}